// round 12
// baseline (speedup 1.0000x reference)
#include <cuda_runtime.h>
#include <cuda_fp16.h>
#include <cstdint>

#define BATCH 8
#define CH    512
#define NTOK  1024
#define NH    8
#define HD    64
#define TC    1536
#define ATT_SCALE 0.125f

// fp16 inputs (original layouts)
__device__ __align__(16) __half g_x[BATCH * CH * NTOK];   // [b][k][m]
__device__ __align__(16) __half g_w[CH * TC];             // [k][j]
__device__ __align__(16) __half g_pw[CH * CH];            // [c][j]

// attention operands, written by QKV epilogue
__device__ __align__(16) __half g_q[BATCH * NH * HD * NTOK]; // [b][h][d][n], pre-scaled
__device__ __align__(16) __half g_k[BATCH * NH * HD * NTOK]; // [b][h][d][n]
__device__ __align__(16) __half g_v[BATCH * NH * NTOK * HD]; // [b][h][n][d]
// attention output, transposed: [b][c][n]
__device__ __align__(16) __half g_o[BATCH * CH * NTOK];

__device__ __forceinline__ uint32_t smem_u32(const void* p) {
    uint32_t a;
    asm("{ .reg .u64 t; cvta.to.shared.u64 t, %1; cvt.u32.u64 %0, t; }"
        : "=r"(a) : "l"(p));
    return a;
}
__device__ __forceinline__ void cp16(uint32_t dst, const void* src) {
    asm volatile("cp.async.cg.shared.global [%0], [%1], 16;"
                 :: "r"(dst), "l"(src));
}
#define CP_COMMIT() asm volatile("cp.async.commit_group;" ::: "memory")
#define CP_WAIT1()  asm volatile("cp.async.wait_group 1;" ::: "memory")
#define CP_WAIT0()  asm volatile("cp.async.wait_group 0;" ::: "memory")

__device__ __forceinline__ void ldsm4t(uint32_t* r, uint32_t a) {
    asm volatile("ldmatrix.sync.aligned.m8n8.x4.trans.shared.b16 {%0,%1,%2,%3}, [%4];"
                 : "=r"(r[0]), "=r"(r[1]), "=r"(r[2]), "=r"(r[3]) : "r"(a));
}
__device__ __forceinline__ void mma16816(float* c, const uint32_t* a, const uint32_t* b) {
    asm volatile(
        "mma.sync.aligned.m16n8k16.row.col.f32.f16.f16.f32 "
        "{%0,%1,%2,%3}, {%4,%5,%6,%7}, {%8,%9}, {%0,%1,%2,%3};"
        : "+f"(c[0]), "+f"(c[1]), "+f"(c[2]), "+f"(c[3])
        : "r"(a[0]), "r"(a[1]), "r"(a[2]), "r"(a[3]), "r"(b[0]), "r"(b[1]));
}
__device__ __forceinline__ uint32_t pack_hh(float a, float b) {
    __half2 t = __floats2half2_rn(a, b);
    return *reinterpret_cast<uint32_t*>(&t);
}

// ===================== prep: fp32 -> fp16 ===================================
__device__ __forceinline__ void cvt4(const float4 v, uint32_t* o, int i) {
    o[i * 2]     = pack_hh(v.x, v.y);
    o[i * 2 + 1] = pack_hh(v.z, v.w);
}
__global__ void prep_x_kernel(const float4* __restrict__ x) {
    int i = blockIdx.x * blockDim.x + threadIdx.x;
    cvt4(x[i], (uint32_t*)g_x, i);
}
__global__ void prep_w_kernel(const float4* __restrict__ w) {
    int i = blockIdx.x * blockDim.x + threadIdx.x;
    cvt4(w[i], (uint32_t*)g_w, i);
}
__global__ void prep_pw_kernel(const float4* __restrict__ w) {
    int i = blockIdx.x * blockDim.x + threadIdx.x;
    cvt4(w[i], (uint32_t*)g_pw, i);
}

// ============ GEMM body (qkv & proj): cp.async pipelined, fp16 =============
// Stage (24 KB): A[64][256B] +0, B[64][128B] +16384.  K-chunks of 64, 2 stages.
__device__ __forceinline__ void gemm_copy_stage(
    uint32_t St, const __half* x, const __half* w,
    int k0, int wstride, int tid)
{
#pragma unroll
    for (int i = 0; i < 4; i++) {
        int q = tid + i * 256, k = q >> 4, c = q & 15;
        uint32_t off = k * 256 + ((c ^ (k & 7)) << 4);
        cp16(St + off, x + (size_t)(k0 + k) * NTOK + c * 8);
    }
#pragma unroll
    for (int i = 0; i < 2; i++) {
        int q = tid + i * 256, k = q >> 3, c = q & 7;
        uint32_t off = k * 128 + ((c ^ (k & 7)) << 4);
        cp16(St + 16384 + off, w + (size_t)(k0 + k) * wstride + c * 8);
    }
}

__device__ __forceinline__ void gemm_pipeline(
    char* sm, const __half* x, const __half* w,
    int wstride, float acc[2][4][4],
    int tid, int lane, int warp_m, int warp_n)
{
    const uint32_t sb = smem_u32(sm);
    const int g = lane >> 3, r8 = lane & 7;

    gemm_copy_stage(sb, x, w, 0, wstride, tid);
    CP_COMMIT();

    for (int ch = 0; ch < 8; ch++) {
        const uint32_t St = sb + (ch & 1) * 24576;
        if (ch < 7) {
            gemm_copy_stage(sb + ((ch + 1) & 1) * 24576, x, w,
                            (ch + 1) * 64, wstride, tid);
            CP_COMMIT();
            CP_WAIT1();
        } else {
            CP_WAIT0();
        }
        __syncthreads();

#pragma unroll
        for (int ks = 0; ks < 4; ks++) {
            uint32_t a[2][4], bb[2][4];
            const int klA = ks * 16 + ((g >> 1) << 3) + r8;
#pragma unroll
            for (int tm = 0; tm < 2; tm++) {
                int cc = ((warp_m * 32 + tm * 16) >> 3) + (g & 1);
                uint32_t off = klA * 256 + ((cc ^ (klA & 7)) << 4);
                ldsm4t(a[tm], St + off);
            }
            const int klB = ks * 16 + ((g & 1) << 3) + r8;
#pragma unroll
            for (int p = 0; p < 2; p++) {
                int cc = ((warp_n * 32 + p * 16) >> 3) + (g >> 1);
                uint32_t off = klB * 128 + ((cc ^ (klB & 7)) << 4);
                ldsm4t(bb[p], St + 16384 + off);
            }
#pragma unroll
            for (int tm = 0; tm < 2; tm++)
#pragma unroll
                for (int tn = 0; tn < 4; tn++)
                    mma16816(acc[tm][tn], a[tm], &bb[tn >> 1][(tn & 1) * 2]);
        }
        __syncthreads();
    }
}

// ===================== Kernel 1: QKV GEMM ==================================
#define GEMM_SMEM 49152

__global__ void __launch_bounds__(256, 2) qkv_hmma_kernel(
    const float* __restrict__ bias)
{
    extern __shared__ char sm[];
    const int tid = threadIdx.x, lane = tid & 31, wid = tid >> 5;
    const int warp_m = wid & 3, warp_n = wid >> 2;
    const int j0 = blockIdx.x * 64, m0 = blockIdx.y * 128, b = blockIdx.z;

    float acc[2][4][4];
#pragma unroll
    for (int tm = 0; tm < 2; tm++)
#pragma unroll
        for (int tn = 0; tn < 4; tn++)
#pragma unroll
            for (int q = 0; q < 4; q++) acc[tm][tn][q] = 0.f;

    gemm_pipeline(sm, g_x + (size_t)b * CH * NTOK + m0,
                  g_w + j0, TC, acc, tid, lane, warp_m, warp_n);

    const int s = j0 >> 9;
    const int h = (j0 >> 6) & (NH - 1);
    const int bhh = b * NH + h;
#pragma unroll
    for (int tn = 0; tn < 4; tn++) {
        const int d = warp_n * 32 + tn * 8 + 2 * (lane & 3);
        const float bv0 = bias[j0 + d], bv1 = bias[j0 + d + 1];
#pragma unroll
        for (int tm = 0; tm < 2; tm++) {
            const int n = m0 + warp_m * 32 + tm * 16 + (lane >> 2);
            float v0 = acc[tm][tn][0] + bv0, v1 = acc[tm][tn][1] + bv1;
            float v2 = acc[tm][tn][2] + bv0, v3 = acc[tm][tn][3] + bv1;
            if (s == 2) {
                size_t a0 = ((size_t)bhh * NTOK + n) * HD + d;
                *(uint32_t*)&g_v[a0] = pack_hh(v0, v1);
                *(uint32_t*)&g_v[a0 + 8 * HD] = pack_hh(v2, v3);
            } else {
                if (s == 0) { v0 *= ATT_SCALE; v1 *= ATT_SCALE; v2 *= ATT_SCALE; v3 *= ATT_SCALE; }
                __half* dq = (s == 0) ? g_q : g_k;
                const size_t b0 = ((size_t)bhh * HD + d) * NTOK;
                const size_t b1 = b0 + NTOK;
                dq[b0 + n]     = __float2half(v0);
                dq[b1 + n]     = __float2half(v1);
                dq[b0 + n + 8] = __float2half(v2);
                dq[b1 + n + 8] = __float2half(v3);
            }
        }
    }
}

// ===================== Kernel 2: Flash attention (fp16, h2exp softmax) ======
// smem: Q [64][256B] at 0 (16 KB); stage s at 16384 + s*32768:
//   K [64][256B] +0, V [128][128B] +16384.  Total 80 KB.
#define ATTN_SMEM 81920

__device__ __forceinline__ void attn_copy_stage(
    uint32_t St, const __half* k_, const __half* v_, int n0, int tid)
{
#pragma unroll
    for (int i = 0; i < 4; i++) {
        int q = tid + i * 256, k = q >> 4, c = q & 15;     // K: 64 rows x 16
        uint32_t off = k * 256 + ((c ^ (k & 7)) << 4);
        cp16(St + off, k_ + (size_t)k * NTOK + n0 + c * 8);
    }
#pragma unroll
    for (int i = 0; i < 4; i++) {
        int q = tid + i * 256, k = q >> 3, c = q & 7;      // V: 128 rows x 8
        uint32_t off = k * 128 + ((c ^ (k & 7)) << 4);
        cp16(St + 16384 + off, v_ + (size_t)(n0 + k) * HD + c * 8);
    }
}

__global__ void __launch_bounds__(256) attn_hmma_kernel()
{
    extern __shared__ char sm[];
    const uint32_t Qb = smem_u32(sm);

    const int tid = threadIdx.x, lane = tid & 31, w = tid >> 5;
    const int g = lane >> 3, r8 = lane & 7;
    const int bh = blockIdx.x;
    const int m0 = blockIdx.y * 128;

    const __half* qp = g_q + (size_t)bh * HD * NTOK;
    const __half* kp = g_k + (size_t)bh * HD * NTOK;
    const __half* vp = g_v + (size_t)bh * NTOK * HD;

    // prefetch KV block 0 while loading Q
    attn_copy_stage(Qb + 16384, kp, vp, 0, tid);
    CP_COMMIT();

#pragma unroll
    for (int i = 0; i < 4; i++) {
        int q = tid + i * 256, k = q >> 4, c = q & 15;
        uint32_t off = k * 256 + ((c ^ (k & 7)) << 4);
        *(int4*)(sm + off) = *(const int4*)(qp + (size_t)k * NTOK + m0 + c * 8);
    }
    __syncthreads();

    uint32_t aq[4][4];
    {
        const int ccA = 2 * w + (g & 1);
#pragma unroll
        for (int ks = 0; ks < 4; ks++) {
            const int klA = ks * 16 + ((g >> 1) << 3) + r8;
            ldsm4t(aq[ks], Qb + klA * 256 + ((ccA ^ (klA & 7)) << 4));
        }
    }

    float mr0 = -1e30f, mr1 = -1e30f, l0 = 0.f, l1 = 0.f;
    float of[8][4];
#pragma unroll
    for (int tn = 0; tn < 8; tn++)
#pragma unroll
        for (int q = 0; q < 4; q++) of[tn][q] = 0.f;

    for (int nb = 0; nb < 8; nb++) {
        const uint32_t St = Qb + 16384 + (nb & 1) * 32768;
        if (nb < 7) {
            attn_copy_stage(Qb + 16384 + ((nb + 1) & 1) * 32768,
                            kp, vp, (nb + 1) * 128, tid);
            CP_COMMIT();
            CP_WAIT1();
        } else {
            CP_WAIT0();
        }
        __syncthreads();

        const uint32_t Kb = St, Vb = St + 16384;

        float sf[16][4];
#pragma unroll
        for (int t = 0; t < 16; t++)
#pragma unroll
            for (int q = 0; q < 4; q++) sf[t][q] = 0.f;

#pragma unroll
        for (int ks = 0; ks < 4; ks++) {
            const int klB = ks * 16 + ((g & 1) << 3) + r8;
#pragma unroll
            for (int tp = 0; tp < 8; tp++) {
                uint32_t bk[4];
                const int cc = tp * 2 + (g >> 1);
                ldsm4t(bk, Kb + klB * 256 + ((cc ^ (klB & 7)) << 4));
                mma16816(sf[2 * tp],     aq[ks], &bk[0]);
                mma16816(sf[2 * tp + 1], aq[ks], &bk[2]);
            }
        }

        // ---- online softmax: exp via h2exp (fp16x2), sums in fp32 ----
        float mx0 = -1e30f, mx1 = -1e30f;
#pragma unroll
        for (int t = 0; t < 16; t++) {
            mx0 = fmaxf(mx0, fmaxf(sf[t][0], sf[t][1]));
            mx1 = fmaxf(mx1, fmaxf(sf[t][2], sf[t][3]));
        }
        mx0 = fmaxf(mx0, __shfl_xor_sync(0xffffffffu, mx0, 1));
        mx0 = fmaxf(mx0, __shfl_xor_sync(0xffffffffu, mx0, 2));
        mx1 = fmaxf(mx1, __shfl_xor_sync(0xffffffffu, mx1, 1));
        mx1 = fmaxf(mx1, __shfl_xor_sync(0xffffffffu, mx1, 2));
        const float nm0 = fmaxf(mr0, mx0), nm1 = fmaxf(mr1, mx1);
        const float a0 = __expf(mr0 - nm0), a1 = __expf(mr1 - nm1);
        mr0 = nm0; mr1 = nm1;

        __half2 eh[16][2];
        float rs0 = 0.f, rs1 = 0.f;
#pragma unroll
        for (int t = 0; t < 16; t++) {
            eh[t][0] = h2exp(__floats2half2_rn(sf[t][0] - nm0, sf[t][1] - nm0));
            eh[t][1] = h2exp(__floats2half2_rn(sf[t][2] - nm1, sf[t][3] - nm1));
            const float2 f0 = __half22float2(eh[t][0]);
            const float2 f1 = __half22float2(eh[t][1]);
            rs0 += f0.x + f0.y;
            rs1 += f1.x + f1.y;
        }
        rs0 += __shfl_xor_sync(0xffffffffu, rs0, 1);
        rs0 += __shfl_xor_sync(0xffffffffu, rs0, 2);
        rs1 += __shfl_xor_sync(0xffffffffu, rs1, 1);
        rs1 += __shfl_xor_sync(0xffffffffu, rs1, 2);
        l0 = l0 * a0 + rs0;
        l1 = l1 * a1 + rs1;
#pragma unroll
        for (int tn = 0; tn < 8; tn++) {
            of[tn][0] *= a0; of[tn][1] *= a0;
            of[tn][2] *= a1; of[tn][3] *= a1;
        }

        // ---- O += P V : eh pairs ARE the P fragments ----
#pragma unroll
        for (int ks = 0; ks < 8; ks++) {
            uint32_t pa[4];
            pa[0] = *(uint32_t*)&eh[2 * ks][0];
            pa[1] = *(uint32_t*)&eh[2 * ks][1];
            pa[2] = *(uint32_t*)&eh[2 * ks + 1][0];
            pa[3] = *(uint32_t*)&eh[2 * ks + 1][1];
            const int klV = ks * 16 + ((g & 1) << 3) + r8;
#pragma unroll
            for (int tp = 0; tp < 4; tp++) {
                uint32_t bv[4];
                const int cc = tp * 2 + (g >> 1);
                ldsm4t(bv, Vb + klV * 128 + ((cc ^ (klV & 7)) << 4));
                mma16816(of[2 * tp],     pa, &bv[0]);
                mma16816(of[2 * tp + 1], pa, &bv[2]);
            }
        }
        __syncthreads();
    }

    // ---- normalize + write O^T fp16 to g_o [b][c][n] ----
    const int b = bh >> 3, h = bh & 7;
    const float inv0 = 1.f / l0, inv1 = 1.f / l1;
    const int r = w * 16 + (lane >> 2);
    const size_t cbase = ((size_t)b * CH + h * HD) * NTOK;
    const int n = m0 + r;
#pragma unroll
    for (int tn = 0; tn < 8; tn++) {
        const int d = tn * 8 + 2 * (lane & 3);
        const size_t c0 = cbase + (size_t)d * NTOK;
        const size_t c1 = c0 + NTOK;
        g_o[c0 + n]     = __float2half(of[tn][0] * inv0);
        g_o[c1 + n]     = __float2half(of[tn][1] * inv0);
        g_o[c0 + n + 8] = __float2half(of[tn][2] * inv1);
        g_o[c1 + n + 8] = __float2half(of[tn][3] * inv1);
    }
}

// ===================== Kernel 3: Proj GEMM =================================
__global__ void __launch_bounds__(256, 2) proj_hmma_kernel(
    const float* __restrict__ bias, float* __restrict__ out)
{
    extern __shared__ char sm[];
    const int tid = threadIdx.x, lane = tid & 31, wid = tid >> 5;
    const int warp_m = wid & 3, warp_n = wid >> 2;
    const int j0 = blockIdx.x * 64, m0 = blockIdx.y * 128, b = blockIdx.z;

    float acc[2][4][4];
#pragma unroll
    for (int tm = 0; tm < 2; tm++)
#pragma unroll
        for (int tn = 0; tn < 4; tn++)
#pragma unroll
            for (int q = 0; q < 4; q++) acc[tm][tn][q] = 0.f;

    gemm_pipeline(sm, g_o + (size_t)b * CH * NTOK + m0,
                  g_pw + j0, CH, acc, tid, lane, warp_m, warp_n);

    float* ob = out + (size_t)b * CH * NTOK;
#pragma unroll
    for (int tn = 0; tn < 4; tn++) {
        const int j = j0 + warp_n * 32 + tn * 8 + 2 * (lane & 3);
        const float bv0 = bias[j], bv1 = bias[j + 1];
        float* p0 = ob + (size_t)j * NTOK;
        float* p1 = p0 + NTOK;
#pragma unroll
        for (int tm = 0; tm < 2; tm++) {
            const int n = m0 + warp_m * 32 + tm * 16 + (lane >> 2);
            p0[n]     = acc[tm][tn][0] + bv0;
            p1[n]     = acc[tm][tn][1] + bv1;
            p0[n + 8] = acc[tm][tn][2] + bv0;
            p1[n + 8] = acc[tm][tn][3] + bv1;
        }
    }
}

// ---------------------------------------------------------------------------
extern "C" void kernel_launch(void* const* d_in, const int* in_sizes, int n_in,
                              void* d_out, int out_size)
{
    const float* x      = (const float*)d_in[0];
    const float* w_qkv  = (const float*)d_in[1];
    const float* b_qkv  = (const float*)d_in[2];
    const float* w_proj = (const float*)d_in[3];
    const float* b_proj = (const float*)d_in[4];
    float* out = (float*)d_out;

    cudaFuncSetAttribute(qkv_hmma_kernel,
                         cudaFuncAttributeMaxDynamicSharedMemorySize, GEMM_SMEM);
    cudaFuncSetAttribute(attn_hmma_kernel,
                         cudaFuncAttributeMaxDynamicSharedMemorySize, ATTN_SMEM);
    cudaFuncSetAttribute(proj_hmma_kernel,
                         cudaFuncAttributeMaxDynamicSharedMemorySize, GEMM_SMEM);

    prep_x_kernel<<<(BATCH * CH * NTOK / 4) / 256, 256>>>((const float4*)x);
    prep_w_kernel<<<(CH * TC / 4) / 256, 256>>>((const float4*)w_qkv);
    prep_pw_kernel<<<(CH * CH / 4) / 256, 256>>>((const float4*)w_proj);
    qkv_hmma_kernel<<<dim3(TC / 64, NTOK / 128, BATCH), 256, GEMM_SMEM>>>(b_qkv);
    attn_hmma_kernel<<<dim3(BATCH * NH, NTOK / 128), 256, ATTN_SMEM>>>();
    proj_hmma_kernel<<<dim3(CH / 64, NTOK / 128, BATCH), 256, GEMM_SMEM>>>(b_proj, out);
}

// round 13
// speedup vs baseline: 1.1169x; 1.1169x over previous
#include <cuda_runtime.h>
#include <cuda_fp16.h>
#include <cstdint>

#define BATCH 8
#define CH    512
#define NTOK  1024
#define NH    8
#define HD    64
#define TC    1536
#define ATT_SCALE 0.125f

// fp16 inputs (original layouts)
__device__ __align__(16) __half g_x[BATCH * CH * NTOK];   // [b][k][m]
__device__ __align__(16) __half g_w[CH * TC];             // [k][j]
__device__ __align__(16) __half g_pw[CH * CH];            // [c][j]

// attention operands, written by QKV epilogue
__device__ __align__(16) __half g_q[BATCH * NH * HD * NTOK]; // [b][h][d][n], pre-scaled
__device__ __align__(16) __half g_k[BATCH * NH * HD * NTOK]; // [b][h][d][n]
__device__ __align__(16) __half g_v[BATCH * NH * NTOK * HD]; // [b][h][n][d]
// attention output, transposed: [b][c][n]
__device__ __align__(16) __half g_o[BATCH * CH * NTOK];

__device__ __forceinline__ uint32_t smem_u32(const void* p) {
    uint32_t a;
    asm("{ .reg .u64 t; cvta.to.shared.u64 t, %1; cvt.u32.u64 %0, t; }"
        : "=r"(a) : "l"(p));
    return a;
}
__device__ __forceinline__ void cp16(uint32_t dst, const void* src) {
    asm volatile("cp.async.cg.shared.global [%0], [%1], 16;"
                 :: "r"(dst), "l"(src));
}
#define CP_COMMIT() asm volatile("cp.async.commit_group;" ::: "memory")
#define CP_WAIT1()  asm volatile("cp.async.wait_group 1;" ::: "memory")
#define CP_WAIT0()  asm volatile("cp.async.wait_group 0;" ::: "memory")

__device__ __forceinline__ void ldsm4t(uint32_t* r, uint32_t a) {
    asm volatile("ldmatrix.sync.aligned.m8n8.x4.trans.shared.b16 {%0,%1,%2,%3}, [%4];"
                 : "=r"(r[0]), "=r"(r[1]), "=r"(r[2]), "=r"(r[3]) : "r"(a));
}
__device__ __forceinline__ void mma16816(float* c, const uint32_t* a, const uint32_t* b) {
    asm volatile(
        "mma.sync.aligned.m16n8k16.row.col.f32.f16.f16.f32 "
        "{%0,%1,%2,%3}, {%4,%5,%6,%7}, {%8,%9}, {%0,%1,%2,%3};"
        : "+f"(c[0]), "+f"(c[1]), "+f"(c[2]), "+f"(c[3])
        : "r"(a[0]), "r"(a[1]), "r"(a[2]), "r"(a[3]), "r"(b[0]), "r"(b[1]));
}
__device__ __forceinline__ uint32_t pack_hh(float a, float b) {
    __half2 t = __floats2half2_rn(a, b);
    return *reinterpret_cast<uint32_t*>(&t);
}

// ===================== prep: fp32 -> fp16 ===================================
__device__ __forceinline__ void cvt4(const float4 v, uint32_t* o, int i) {
    o[i * 2]     = pack_hh(v.x, v.y);
    o[i * 2 + 1] = pack_hh(v.z, v.w);
}
__global__ void prep_x_kernel(const float4* __restrict__ x) {
    int i = blockIdx.x * blockDim.x + threadIdx.x;
    cvt4(x[i], (uint32_t*)g_x, i);
}
__global__ void prep_w_kernel(const float4* __restrict__ w) {
    int i = blockIdx.x * blockDim.x + threadIdx.x;
    cvt4(w[i], (uint32_t*)g_w, i);
}
__global__ void prep_pw_kernel(const float4* __restrict__ w) {
    int i = blockIdx.x * blockDim.x + threadIdx.x;
    cvt4(w[i], (uint32_t*)g_pw, i);
}

// ============ GEMM body (qkv & proj): cp.async pipelined, fp16 =============
// Stage (24 KB): A[64][256B] +0, B[64][128B] +16384.  K-chunks of 64, 2 stages.
__device__ __forceinline__ void gemm_copy_stage(
    uint32_t St, const __half* x, const __half* w,
    int k0, int wstride, int tid)
{
#pragma unroll
    for (int i = 0; i < 4; i++) {
        int q = tid + i * 256, k = q >> 4, c = q & 15;
        uint32_t off = k * 256 + ((c ^ (k & 7)) << 4);
        cp16(St + off, x + (size_t)(k0 + k) * NTOK + c * 8);
    }
#pragma unroll
    for (int i = 0; i < 2; i++) {
        int q = tid + i * 256, k = q >> 3, c = q & 7;
        uint32_t off = k * 128 + ((c ^ (k & 7)) << 4);
        cp16(St + 16384 + off, w + (size_t)(k0 + k) * wstride + c * 8);
    }
}

__device__ __forceinline__ void gemm_pipeline(
    char* sm, const __half* x, const __half* w,
    int wstride, float acc[2][4][4],
    int tid, int lane, int warp_m, int warp_n)
{
    const uint32_t sb = smem_u32(sm);
    const int g = lane >> 3, r8 = lane & 7;

    gemm_copy_stage(sb, x, w, 0, wstride, tid);
    CP_COMMIT();

    for (int ch = 0; ch < 8; ch++) {
        const uint32_t St = sb + (ch & 1) * 24576;
        if (ch < 7) {
            gemm_copy_stage(sb + ((ch + 1) & 1) * 24576, x, w,
                            (ch + 1) * 64, wstride, tid);
            CP_COMMIT();
            CP_WAIT1();
        } else {
            CP_WAIT0();
        }
        __syncthreads();

#pragma unroll
        for (int ks = 0; ks < 4; ks++) {
            uint32_t a[2][4], bb[2][4];
            const int klA = ks * 16 + ((g >> 1) << 3) + r8;
#pragma unroll
            for (int tm = 0; tm < 2; tm++) {
                int cc = ((warp_m * 32 + tm * 16) >> 3) + (g & 1);
                uint32_t off = klA * 256 + ((cc ^ (klA & 7)) << 4);
                ldsm4t(a[tm], St + off);
            }
            const int klB = ks * 16 + ((g & 1) << 3) + r8;
#pragma unroll
            for (int p = 0; p < 2; p++) {
                int cc = ((warp_n * 32 + p * 16) >> 3) + (g >> 1);
                uint32_t off = klB * 128 + ((cc ^ (klB & 7)) << 4);
                ldsm4t(bb[p], St + 16384 + off);
            }
#pragma unroll
            for (int tm = 0; tm < 2; tm++)
#pragma unroll
                for (int tn = 0; tn < 4; tn++)
                    mma16816(acc[tm][tn], a[tm], &bb[tn >> 1][(tn & 1) * 2]);
        }
        __syncthreads();
    }
}

// ===================== Kernel 1: QKV GEMM ==================================
#define GEMM_SMEM 49152

__global__ void __launch_bounds__(256, 2) qkv_hmma_kernel(
    const float* __restrict__ bias)
{
    extern __shared__ char sm[];
    const int tid = threadIdx.x, lane = tid & 31, wid = tid >> 5;
    const int warp_m = wid & 3, warp_n = wid >> 2;
    const int j0 = blockIdx.x * 64, m0 = blockIdx.y * 128, b = blockIdx.z;

    float acc[2][4][4];
#pragma unroll
    for (int tm = 0; tm < 2; tm++)
#pragma unroll
        for (int tn = 0; tn < 4; tn++)
#pragma unroll
            for (int q = 0; q < 4; q++) acc[tm][tn][q] = 0.f;

    gemm_pipeline(sm, g_x + (size_t)b * CH * NTOK + m0,
                  g_w + j0, TC, acc, tid, lane, warp_m, warp_n);

    const int s = j0 >> 9;
    const int h = (j0 >> 6) & (NH - 1);
    const int bhh = b * NH + h;
#pragma unroll
    for (int tn = 0; tn < 4; tn++) {
        const int d = warp_n * 32 + tn * 8 + 2 * (lane & 3);
        const float bv0 = bias[j0 + d], bv1 = bias[j0 + d + 1];
#pragma unroll
        for (int tm = 0; tm < 2; tm++) {
            const int n = m0 + warp_m * 32 + tm * 16 + (lane >> 2);
            float v0 = acc[tm][tn][0] + bv0, v1 = acc[tm][tn][1] + bv1;
            float v2 = acc[tm][tn][2] + bv0, v3 = acc[tm][tn][3] + bv1;
            if (s == 2) {
                size_t a0 = ((size_t)bhh * NTOK + n) * HD + d;
                *(uint32_t*)&g_v[a0] = pack_hh(v0, v1);
                *(uint32_t*)&g_v[a0 + 8 * HD] = pack_hh(v2, v3);
            } else {
                if (s == 0) { v0 *= ATT_SCALE; v1 *= ATT_SCALE; v2 *= ATT_SCALE; v3 *= ATT_SCALE; }
                __half* dq = (s == 0) ? g_q : g_k;
                const size_t b0 = ((size_t)bhh * HD + d) * NTOK;
                const size_t b1 = b0 + NTOK;
                dq[b0 + n]     = __float2half(v0);
                dq[b1 + n]     = __float2half(v1);
                dq[b0 + n + 8] = __float2half(v2);
                dq[b1 + n + 8] = __float2half(v3);
            }
        }
    }
}

// ===================== Kernel 2: Flash attention (fp16, __expf softmax) =====
// smem: Q [64][256B] at 0 (16 KB); stage s at 16384 + s*32768:
//   K [64][256B] +0, V [128][128B] +16384.  Total 80 KB.
#define ATTN_SMEM 81920

__device__ __forceinline__ void attn_copy_stage(
    uint32_t St, const __half* k_, const __half* v_, int n0, int tid)
{
#pragma unroll
    for (int i = 0; i < 4; i++) {
        int q = tid + i * 256, k = q >> 4, c = q & 15;     // K: 64 rows x 16
        uint32_t off = k * 256 + ((c ^ (k & 7)) << 4);
        cp16(St + off, k_ + (size_t)k * NTOK + n0 + c * 8);
    }
#pragma unroll
    for (int i = 0; i < 4; i++) {
        int q = tid + i * 256, k = q >> 3, c = q & 7;      // V: 128 rows x 8
        uint32_t off = k * 128 + ((c ^ (k & 7)) << 4);
        cp16(St + 16384 + off, v_ + (size_t)(n0 + k) * HD + c * 8);
    }
}

__global__ void __launch_bounds__(256) attn_hmma_kernel()
{
    extern __shared__ char sm[];
    const uint32_t Qb = smem_u32(sm);

    const int tid = threadIdx.x, lane = tid & 31, w = tid >> 5;
    const int g = lane >> 3, r8 = lane & 7;
    const int bh = blockIdx.x;
    const int m0 = blockIdx.y * 128;

    const __half* qp = g_q + (size_t)bh * HD * NTOK;
    const __half* kp = g_k + (size_t)bh * HD * NTOK;
    const __half* vp = g_v + (size_t)bh * NTOK * HD;

    // prefetch KV block 0 while loading Q
    attn_copy_stage(Qb + 16384, kp, vp, 0, tid);
    CP_COMMIT();

#pragma unroll
    for (int i = 0; i < 4; i++) {
        int q = tid + i * 256, k = q >> 4, c = q & 15;
        uint32_t off = k * 256 + ((c ^ (k & 7)) << 4);
        *(int4*)(sm + off) = *(const int4*)(qp + (size_t)k * NTOK + m0 + c * 8);
    }
    __syncthreads();

    uint32_t aq[4][4];
    {
        const int ccA = 2 * w + (g & 1);
#pragma unroll
        for (int ks = 0; ks < 4; ks++) {
            const int klA = ks * 16 + ((g >> 1) << 3) + r8;
            ldsm4t(aq[ks], Qb + klA * 256 + ((ccA ^ (klA & 7)) << 4));
        }
    }

    float mr0 = -1e30f, mr1 = -1e30f, l0 = 0.f, l1 = 0.f;
    float of[8][4];
#pragma unroll
    for (int tn = 0; tn < 8; tn++)
#pragma unroll
        for (int q = 0; q < 4; q++) of[tn][q] = 0.f;

    for (int nb = 0; nb < 8; nb++) {
        const uint32_t St = Qb + 16384 + (nb & 1) * 32768;
        if (nb < 7) {
            attn_copy_stage(Qb + 16384 + ((nb + 1) & 1) * 32768,
                            kp, vp, (nb + 1) * 128, tid);
            CP_COMMIT();
            CP_WAIT1();
        } else {
            CP_WAIT0();
        }
        __syncthreads();

        const uint32_t Kb = St, Vb = St + 16384;

        float sf[16][4];
#pragma unroll
        for (int t = 0; t < 16; t++)
#pragma unroll
            for (int q = 0; q < 4; q++) sf[t][q] = 0.f;

#pragma unroll
        for (int ks = 0; ks < 4; ks++) {
            const int klB = ks * 16 + ((g & 1) << 3) + r8;
#pragma unroll
            for (int tp = 0; tp < 8; tp++) {
                uint32_t bk[4];
                const int cc = tp * 2 + (g >> 1);
                ldsm4t(bk, Kb + klB * 256 + ((cc ^ (klB & 7)) << 4));
                mma16816(sf[2 * tp],     aq[ks], &bk[0]);
                mma16816(sf[2 * tp + 1], aq[ks], &bk[2]);
            }
        }

        // ---- online softmax (__expf, fp32) ----
        float mx0 = -1e30f, mx1 = -1e30f;
#pragma unroll
        for (int t = 0; t < 16; t++) {
            mx0 = fmaxf(mx0, fmaxf(sf[t][0], sf[t][1]));
            mx1 = fmaxf(mx1, fmaxf(sf[t][2], sf[t][3]));
        }
        mx0 = fmaxf(mx0, __shfl_xor_sync(0xffffffffu, mx0, 1));
        mx0 = fmaxf(mx0, __shfl_xor_sync(0xffffffffu, mx0, 2));
        mx1 = fmaxf(mx1, __shfl_xor_sync(0xffffffffu, mx1, 1));
        mx1 = fmaxf(mx1, __shfl_xor_sync(0xffffffffu, mx1, 2));
        const float nm0 = fmaxf(mr0, mx0), nm1 = fmaxf(mr1, mx1);
        const float a0 = __expf(mr0 - nm0), a1 = __expf(mr1 - nm1);
        mr0 = nm0; mr1 = nm1;
        float rs0 = 0.f, rs1 = 0.f;
#pragma unroll
        for (int t = 0; t < 16; t++) {
            sf[t][0] = __expf(sf[t][0] - nm0);
            sf[t][1] = __expf(sf[t][1] - nm0);
            sf[t][2] = __expf(sf[t][2] - nm1);
            sf[t][3] = __expf(sf[t][3] - nm1);
            rs0 += sf[t][0] + sf[t][1];
            rs1 += sf[t][2] + sf[t][3];
        }
        rs0 += __shfl_xor_sync(0xffffffffu, rs0, 1);
        rs0 += __shfl_xor_sync(0xffffffffu, rs0, 2);
        rs1 += __shfl_xor_sync(0xffffffffu, rs1, 1);
        rs1 += __shfl_xor_sync(0xffffffffu, rs1, 2);
        l0 = l0 * a0 + rs0;
        l1 = l1 * a1 + rs1;
#pragma unroll
        for (int tn = 0; tn < 8; tn++) {
            of[tn][0] *= a0; of[tn][1] *= a0;
            of[tn][2] *= a1; of[tn][3] *= a1;
        }

        // ---- O += P V : P packed to fp16 fragments ----
#pragma unroll
        for (int ks = 0; ks < 8; ks++) {
            uint32_t pa[4];
            pa[0] = pack_hh(sf[2 * ks][0],     sf[2 * ks][1]);
            pa[1] = pack_hh(sf[2 * ks][2],     sf[2 * ks][3]);
            pa[2] = pack_hh(sf[2 * ks + 1][0], sf[2 * ks + 1][1]);
            pa[3] = pack_hh(sf[2 * ks + 1][2], sf[2 * ks + 1][3]);
            const int klV = ks * 16 + ((g & 1) << 3) + r8;
#pragma unroll
            for (int tp = 0; tp < 4; tp++) {
                uint32_t bv[4];
                const int cc = tp * 2 + (g >> 1);
                ldsm4t(bv, Vb + klV * 128 + ((cc ^ (klV & 7)) << 4));
                mma16816(of[2 * tp],     pa, &bv[0]);
                mma16816(of[2 * tp + 1], pa, &bv[2]);
            }
        }
        __syncthreads();
    }

    // ---- normalize + write O^T fp16 to g_o [b][c][n] ----
    const int b = bh >> 3, h = bh & 7;
    const float inv0 = 1.f / l0, inv1 = 1.f / l1;
    const int r = w * 16 + (lane >> 2);
    const size_t cbase = ((size_t)b * CH + h * HD) * NTOK;
    const int n = m0 + r;
#pragma unroll
    for (int tn = 0; tn < 8; tn++) {
        const int d = tn * 8 + 2 * (lane & 3);
        const size_t c0 = cbase + (size_t)d * NTOK;
        const size_t c1 = c0 + NTOK;
        g_o[c0 + n]     = __float2half(of[tn][0] * inv0);
        g_o[c1 + n]     = __float2half(of[tn][1] * inv0);
        g_o[c0 + n + 8] = __float2half(of[tn][2] * inv1);
        g_o[c1 + n + 8] = __float2half(of[tn][3] * inv1);
    }
}

// ===================== Kernel 3: Proj GEMM =================================
__global__ void __launch_bounds__(256, 2) proj_hmma_kernel(
    const float* __restrict__ bias, float* __restrict__ out)
{
    extern __shared__ char sm[];
    const int tid = threadIdx.x, lane = tid & 31, wid = tid >> 5;
    const int warp_m = wid & 3, warp_n = wid >> 2;
    const int j0 = blockIdx.x * 64, m0 = blockIdx.y * 128, b = blockIdx.z;

    float acc[2][4][4];
#pragma unroll
    for (int tm = 0; tm < 2; tm++)
#pragma unroll
        for (int tn = 0; tn < 4; tn++)
#pragma unroll
            for (int q = 0; q < 4; q++) acc[tm][tn][q] = 0.f;

    gemm_pipeline(sm, g_o + (size_t)b * CH * NTOK + m0,
                  g_pw + j0, CH, acc, tid, lane, warp_m, warp_n);

    float* ob = out + (size_t)b * CH * NTOK;
#pragma unroll
    for (int tn = 0; tn < 4; tn++) {
        const int j = j0 + warp_n * 32 + tn * 8 + 2 * (lane & 3);
        const float bv0 = bias[j], bv1 = bias[j + 1];
        float* p0 = ob + (size_t)j * NTOK;
        float* p1 = p0 + NTOK;
#pragma unroll
        for (int tm = 0; tm < 2; tm++) {
            const int n = m0 + warp_m * 32 + tm * 16 + (lane >> 2);
            p0[n]     = acc[tm][tn][0] + bv0;
            p1[n]     = acc[tm][tn][1] + bv1;
            p0[n + 8] = acc[tm][tn][2] + bv0;
            p1[n + 8] = acc[tm][tn][3] + bv1;
        }
    }
}

// ---------------------------------------------------------------------------
extern "C" void kernel_launch(void* const* d_in, const int* in_sizes, int n_in,
                              void* d_out, int out_size)
{
    const float* x      = (const float*)d_in[0];
    const float* w_qkv  = (const float*)d_in[1];
    const float* b_qkv  = (const float*)d_in[2];
    const float* w_proj = (const float*)d_in[3];
    const float* b_proj = (const float*)d_in[4];
    float* out = (float*)d_out;

    cudaFuncSetAttribute(qkv_hmma_kernel,
                         cudaFuncAttributeMaxDynamicSharedMemorySize, GEMM_SMEM);
    cudaFuncSetAttribute(attn_hmma_kernel,
                         cudaFuncAttributeMaxDynamicSharedMemorySize, ATTN_SMEM);
    cudaFuncSetAttribute(proj_hmma_kernel,
                         cudaFuncAttributeMaxDynamicSharedMemorySize, GEMM_SMEM);

    prep_x_kernel<<<(BATCH * CH * NTOK / 4) / 256, 256>>>((const float4*)x);
    prep_w_kernel<<<(CH * TC / 4) / 256, 256>>>((const float4*)w_qkv);
    prep_pw_kernel<<<(CH * CH / 4) / 256, 256>>>((const float4*)w_proj);
    qkv_hmma_kernel<<<dim3(TC / 64, NTOK / 128, BATCH), 256, GEMM_SMEM>>>(b_qkv);
    attn_hmma_kernel<<<dim3(BATCH * NH, NTOK / 128), 256, ATTN_SMEM>>>();
    proj_hmma_kernel<<<dim3(CH / 64, NTOK / 128, BATCH), 256, GEMM_SMEM>>>(b_proj, out);
}

// round 14
// speedup vs baseline: 1.1771x; 1.0539x over previous
#include <cuda_runtime.h>
#include <cuda_fp16.h>
#include <cstdint>

#define BATCH 8
#define CH    512
#define NTOK  1024
#define NH    8
#define HD    64
#define TC    1536
#define ATT_SCALE 0.125f

// fp16 inputs (original layouts)
__device__ __align__(16) __half g_x[BATCH * CH * NTOK];   // [b][k][m]
__device__ __align__(16) __half g_w[CH * TC];             // [k][j]
__device__ __align__(16) __half g_pw[CH * CH];            // [c][j]

// attention operands, written by QKV epilogue
__device__ __align__(16) __half g_q[BATCH * NH * HD * NTOK]; // [b][h][d][n], pre-scaled
__device__ __align__(16) __half g_k[BATCH * NH * HD * NTOK]; // [b][h][d][n]
__device__ __align__(16) __half g_v[BATCH * NH * NTOK * HD]; // [b][h][n][d]
// attention output, transposed: [b][c][n]
__device__ __align__(16) __half g_o[BATCH * CH * NTOK];

__device__ __forceinline__ uint32_t smem_u32(const void* p) {
    uint32_t a;
    asm("{ .reg .u64 t; cvta.to.shared.u64 t, %1; cvt.u32.u64 %0, t; }"
        : "=r"(a) : "l"(p));
    return a;
}
__device__ __forceinline__ void cp16(uint32_t dst, const void* src) {
    asm volatile("cp.async.cg.shared.global [%0], [%1], 16;"
                 :: "r"(dst), "l"(src));
}
#define CP_COMMIT() asm volatile("cp.async.commit_group;" ::: "memory")
#define CP_WAIT1()  asm volatile("cp.async.wait_group 1;" ::: "memory")
#define CP_WAIT0()  asm volatile("cp.async.wait_group 0;" ::: "memory")

__device__ __forceinline__ void ldsm4t(uint32_t* r, uint32_t a) {
    asm volatile("ldmatrix.sync.aligned.m8n8.x4.trans.shared.b16 {%0,%1,%2,%3}, [%4];"
                 : "=r"(r[0]), "=r"(r[1]), "=r"(r[2]), "=r"(r[3]) : "r"(a));
}
__device__ __forceinline__ void mma16816(float* c, const uint32_t* a, const uint32_t* b) {
    asm volatile(
        "mma.sync.aligned.m16n8k16.row.col.f32.f16.f16.f32 "
        "{%0,%1,%2,%3}, {%4,%5,%6,%7}, {%8,%9}, {%0,%1,%2,%3};"
        : "+f"(c[0]), "+f"(c[1]), "+f"(c[2]), "+f"(c[3])
        : "r"(a[0]), "r"(a[1]), "r"(a[2]), "r"(a[3]), "r"(b[0]), "r"(b[1]));
}
__device__ __forceinline__ uint32_t pack_hh(float a, float b) {
    __half2 t = __floats2half2_rn(a, b);
    return *reinterpret_cast<uint32_t*>(&t);
}

// ===================== prep: fp32 -> fp16 ===================================
__device__ __forceinline__ void cvt4(const float4 v, uint32_t* o, int i) {
    o[i * 2]     = pack_hh(v.x, v.y);
    o[i * 2 + 1] = pack_hh(v.z, v.w);
}
__global__ void prep_x_kernel(const float4* __restrict__ x) {
    int i = blockIdx.x * blockDim.x + threadIdx.x;
    cvt4(x[i], (uint32_t*)g_x, i);
}
__global__ void prep_w_kernel(const float4* __restrict__ w) {
    int i = blockIdx.x * blockDim.x + threadIdx.x;
    cvt4(w[i], (uint32_t*)g_w, i);
}
__global__ void prep_pw_kernel(const float4* __restrict__ w) {
    int i = blockIdx.x * blockDim.x + threadIdx.x;
    cvt4(w[i], (uint32_t*)g_pw, i);
}

// ============ GEMM body (qkv & proj): 128x128 CTA tile, cp.async ===========
// Stage (32 KB): A[64][256B] +0, B[64][256B] +16384.  K-chunks of 64, 2 stages.
// Warp grid 4(m) x 2(n); warp tile 32 m x 64 j.
__device__ __forceinline__ void gemm_copy_stage(
    uint32_t St, const __half* x, const __half* w,
    int k0, int wstride, int tid)
{
#pragma unroll
    for (int i = 0; i < 4; i++) {
        int q = tid + i * 256, k = q >> 4, c = q & 15;
        uint32_t off = k * 256 + ((c ^ (k & 7)) << 4);
        cp16(St + off, x + (size_t)(k0 + k) * NTOK + c * 8);
    }
#pragma unroll
    for (int i = 0; i < 4; i++) {
        int q = tid + i * 256, k = q >> 4, c = q & 15;
        uint32_t off = k * 256 + ((c ^ (k & 7)) << 4);
        cp16(St + 16384 + off, w + (size_t)(k0 + k) * wstride + c * 8);
    }
}

__device__ __forceinline__ void gemm_pipeline(
    char* sm, const __half* x, const __half* w,
    int wstride, float acc[2][8][4],
    int tid, int lane, int warp_m, int warp_n)
{
    const uint32_t sb = smem_u32(sm);
    const int g = lane >> 3, r8 = lane & 7;

    gemm_copy_stage(sb, x, w, 0, wstride, tid);
    CP_COMMIT();

    for (int ch = 0; ch < 8; ch++) {
        const uint32_t St = sb + (ch & 1) * 32768;
        if (ch < 7) {
            gemm_copy_stage(sb + ((ch + 1) & 1) * 32768, x, w,
                            (ch + 1) * 64, wstride, tid);
            CP_COMMIT();
            CP_WAIT1();
        } else {
            CP_WAIT0();
        }
        __syncthreads();

#pragma unroll
        for (int ks = 0; ks < 4; ks++) {
            uint32_t a[2][4], bb[4][4];
            const int klA = ks * 16 + ((g >> 1) << 3) + r8;
#pragma unroll
            for (int tm = 0; tm < 2; tm++) {
                int cc = ((warp_m * 32 + tm * 16) >> 3) + (g & 1);
                uint32_t off = klA * 256 + ((cc ^ (klA & 7)) << 4);
                ldsm4t(a[tm], St + off);
            }
            const int klB = ks * 16 + ((g & 1) << 3) + r8;
#pragma unroll
            for (int p = 0; p < 4; p++) {
                int cc = ((warp_n * 64 + p * 16) >> 3) + (g >> 1);
                uint32_t off = klB * 256 + ((cc ^ (klB & 7)) << 4);
                ldsm4t(bb[p], St + 16384 + off);
            }
#pragma unroll
            for (int tm = 0; tm < 2; tm++)
#pragma unroll
                for (int tn = 0; tn < 8; tn++)
                    mma16816(acc[tm][tn], a[tm], &bb[tn >> 1][(tn & 1) * 2]);
        }
        __syncthreads();
    }
}

// ===================== Kernel 1: QKV GEMM ==================================
#define GEMM_SMEM 65536

__global__ void __launch_bounds__(256, 2) qkv_hmma_kernel(
    const float* __restrict__ bias)
{
    extern __shared__ char sm[];
    const int tid = threadIdx.x, lane = tid & 31, wid = tid >> 5;
    const int warp_m = wid & 3, warp_n = wid >> 2;
    const int j0 = blockIdx.x * 128, m0 = blockIdx.y * 128, b = blockIdx.z;

    float acc[2][8][4];
#pragma unroll
    for (int tm = 0; tm < 2; tm++)
#pragma unroll
        for (int tn = 0; tn < 8; tn++)
#pragma unroll
            for (int q = 0; q < 4; q++) acc[tm][tn][q] = 0.f;

    gemm_pipeline(sm, g_x + (size_t)b * CH * NTOK + m0,
                  g_w + j0, TC, acc, tid, lane, warp_m, warp_n);

    // epilogue: 128-tile never crosses the s boundary (512 % 128 == 0)
    const int s = j0 >> 9;
#pragma unroll
    for (int tn = 0; tn < 8; tn++) {
        const int j = j0 + warp_n * 64 + tn * 8 + 2 * (lane & 3);
        const int h = (j >> 6) & (NH - 1);
        const int d = j & (HD - 1);
        const int bhh = b * NH + h;
        const float bv0 = bias[j], bv1 = bias[j + 1];
#pragma unroll
        for (int tm = 0; tm < 2; tm++) {
            const int n = m0 + warp_m * 32 + tm * 16 + (lane >> 2);
            float v0 = acc[tm][tn][0] + bv0, v1 = acc[tm][tn][1] + bv1;
            float v2 = acc[tm][tn][2] + bv0, v3 = acc[tm][tn][3] + bv1;
            if (s == 2) {
                size_t a0 = ((size_t)bhh * NTOK + n) * HD + d;
                *(uint32_t*)&g_v[a0] = pack_hh(v0, v1);
                *(uint32_t*)&g_v[a0 + 8 * HD] = pack_hh(v2, v3);
            } else {
                if (s == 0) { v0 *= ATT_SCALE; v1 *= ATT_SCALE; v2 *= ATT_SCALE; v3 *= ATT_SCALE; }
                __half* dq = (s == 0) ? g_q : g_k;
                const size_t b0 = ((size_t)bhh * HD + d) * NTOK;
                const size_t b1 = b0 + NTOK;
                dq[b0 + n]     = __float2half(v0);
                dq[b1 + n]     = __float2half(v1);
                dq[b0 + n + 8] = __float2half(v2);
                dq[b1 + n + 8] = __float2half(v3);
            }
        }
    }
}

// ===================== Kernel 2: Flash attention (unchanged) ================
// smem: Q [64][256B] at 0 (16 KB); stage s at 16384 + s*32768:
//   K [64][256B] +0, V [128][128B] +16384.  Total 80 KB.
#define ATTN_SMEM 81920

__device__ __forceinline__ void attn_copy_stage(
    uint32_t St, const __half* k_, const __half* v_, int n0, int tid)
{
#pragma unroll
    for (int i = 0; i < 4; i++) {
        int q = tid + i * 256, k = q >> 4, c = q & 15;     // K: 64 rows x 16
        uint32_t off = k * 256 + ((c ^ (k & 7)) << 4);
        cp16(St + off, k_ + (size_t)k * NTOK + n0 + c * 8);
    }
#pragma unroll
    for (int i = 0; i < 4; i++) {
        int q = tid + i * 256, k = q >> 3, c = q & 7;      // V: 128 rows x 8
        uint32_t off = k * 128 + ((c ^ (k & 7)) << 4);
        cp16(St + 16384 + off, v_ + (size_t)(n0 + k) * HD + c * 8);
    }
}

__global__ void __launch_bounds__(256) attn_hmma_kernel()
{
    extern __shared__ char sm[];
    const uint32_t Qb = smem_u32(sm);

    const int tid = threadIdx.x, lane = tid & 31, w = tid >> 5;
    const int g = lane >> 3, r8 = lane & 7;
    const int bh = blockIdx.x;
    const int m0 = blockIdx.y * 128;

    const __half* qp = g_q + (size_t)bh * HD * NTOK;
    const __half* kp = g_k + (size_t)bh * HD * NTOK;
    const __half* vp = g_v + (size_t)bh * NTOK * HD;

    attn_copy_stage(Qb + 16384, kp, vp, 0, tid);
    CP_COMMIT();

#pragma unroll
    for (int i = 0; i < 4; i++) {
        int q = tid + i * 256, k = q >> 4, c = q & 15;
        uint32_t off = k * 256 + ((c ^ (k & 7)) << 4);
        *(int4*)(sm + off) = *(const int4*)(qp + (size_t)k * NTOK + m0 + c * 8);
    }
    __syncthreads();

    uint32_t aq[4][4];
    {
        const int ccA = 2 * w + (g & 1);
#pragma unroll
        for (int ks = 0; ks < 4; ks++) {
            const int klA = ks * 16 + ((g >> 1) << 3) + r8;
            ldsm4t(aq[ks], Qb + klA * 256 + ((ccA ^ (klA & 7)) << 4));
        }
    }

    float mr0 = -1e30f, mr1 = -1e30f, l0 = 0.f, l1 = 0.f;
    float of[8][4];
#pragma unroll
    for (int tn = 0; tn < 8; tn++)
#pragma unroll
        for (int q = 0; q < 4; q++) of[tn][q] = 0.f;

    for (int nb = 0; nb < 8; nb++) {
        const uint32_t St = Qb + 16384 + (nb & 1) * 32768;
        if (nb < 7) {
            attn_copy_stage(Qb + 16384 + ((nb + 1) & 1) * 32768,
                            kp, vp, (nb + 1) * 128, tid);
            CP_COMMIT();
            CP_WAIT1();
        } else {
            CP_WAIT0();
        }
        __syncthreads();

        const uint32_t Kb = St, Vb = St + 16384;

        float sf[16][4];
#pragma unroll
        for (int t = 0; t < 16; t++)
#pragma unroll
            for (int q = 0; q < 4; q++) sf[t][q] = 0.f;

#pragma unroll
        for (int ks = 0; ks < 4; ks++) {
            const int klB = ks * 16 + ((g & 1) << 3) + r8;
#pragma unroll
            for (int tp = 0; tp < 8; tp++) {
                uint32_t bk[4];
                const int cc = tp * 2 + (g >> 1);
                ldsm4t(bk, Kb + klB * 256 + ((cc ^ (klB & 7)) << 4));
                mma16816(sf[2 * tp],     aq[ks], &bk[0]);
                mma16816(sf[2 * tp + 1], aq[ks], &bk[2]);
            }
        }

        float mx0 = -1e30f, mx1 = -1e30f;
#pragma unroll
        for (int t = 0; t < 16; t++) {
            mx0 = fmaxf(mx0, fmaxf(sf[t][0], sf[t][1]));
            mx1 = fmaxf(mx1, fmaxf(sf[t][2], sf[t][3]));
        }
        mx0 = fmaxf(mx0, __shfl_xor_sync(0xffffffffu, mx0, 1));
        mx0 = fmaxf(mx0, __shfl_xor_sync(0xffffffffu, mx0, 2));
        mx1 = fmaxf(mx1, __shfl_xor_sync(0xffffffffu, mx1, 1));
        mx1 = fmaxf(mx1, __shfl_xor_sync(0xffffffffu, mx1, 2));
        const float nm0 = fmaxf(mr0, mx0), nm1 = fmaxf(mr1, mx1);
        const float a0 = __expf(mr0 - nm0), a1 = __expf(mr1 - nm1);
        mr0 = nm0; mr1 = nm1;
        float rs0 = 0.f, rs1 = 0.f;
#pragma unroll
        for (int t = 0; t < 16; t++) {
            sf[t][0] = __expf(sf[t][0] - nm0);
            sf[t][1] = __expf(sf[t][1] - nm0);
            sf[t][2] = __expf(sf[t][2] - nm1);
            sf[t][3] = __expf(sf[t][3] - nm1);
            rs0 += sf[t][0] + sf[t][1];
            rs1 += sf[t][2] + sf[t][3];
        }
        rs0 += __shfl_xor_sync(0xffffffffu, rs0, 1);
        rs0 += __shfl_xor_sync(0xffffffffu, rs0, 2);
        rs1 += __shfl_xor_sync(0xffffffffu, rs1, 1);
        rs1 += __shfl_xor_sync(0xffffffffu, rs1, 2);
        l0 = l0 * a0 + rs0;
        l1 = l1 * a1 + rs1;
#pragma unroll
        for (int tn = 0; tn < 8; tn++) {
            of[tn][0] *= a0; of[tn][1] *= a0;
            of[tn][2] *= a1; of[tn][3] *= a1;
        }

#pragma unroll
        for (int ks = 0; ks < 8; ks++) {
            uint32_t pa[4];
            pa[0] = pack_hh(sf[2 * ks][0],     sf[2 * ks][1]);
            pa[1] = pack_hh(sf[2 * ks][2],     sf[2 * ks][3]);
            pa[2] = pack_hh(sf[2 * ks + 1][0], sf[2 * ks + 1][1]);
            pa[3] = pack_hh(sf[2 * ks + 1][2], sf[2 * ks + 1][3]);
            const int klV = ks * 16 + ((g & 1) << 3) + r8;
#pragma unroll
            for (int tp = 0; tp < 4; tp++) {
                uint32_t bv[4];
                const int cc = tp * 2 + (g >> 1);
                ldsm4t(bv, Vb + klV * 128 + ((cc ^ (klV & 7)) << 4));
                mma16816(of[2 * tp],     pa, &bv[0]);
                mma16816(of[2 * tp + 1], pa, &bv[2]);
            }
        }
        __syncthreads();
    }

    const int b = bh >> 3, h = bh & 7;
    const float inv0 = 1.f / l0, inv1 = 1.f / l1;
    const int r = w * 16 + (lane >> 2);
    const size_t cbase = ((size_t)b * CH + h * HD) * NTOK;
    const int n = m0 + r;
#pragma unroll
    for (int tn = 0; tn < 8; tn++) {
        const int d = tn * 8 + 2 * (lane & 3);
        const size_t c0 = cbase + (size_t)d * NTOK;
        const size_t c1 = c0 + NTOK;
        g_o[c0 + n]     = __float2half(of[tn][0] * inv0);
        g_o[c1 + n]     = __float2half(of[tn][1] * inv0);
        g_o[c0 + n + 8] = __float2half(of[tn][2] * inv1);
        g_o[c1 + n + 8] = __float2half(of[tn][3] * inv1);
    }
}

// ===================== Kernel 3: Proj GEMM =================================
__global__ void __launch_bounds__(256, 2) proj_hmma_kernel(
    const float* __restrict__ bias, float* __restrict__ out)
{
    extern __shared__ char sm[];
    const int tid = threadIdx.x, lane = tid & 31, wid = tid >> 5;
    const int warp_m = wid & 3, warp_n = wid >> 2;
    const int j0 = blockIdx.x * 128, m0 = blockIdx.y * 128, b = blockIdx.z;

    float acc[2][8][4];
#pragma unroll
    for (int tm = 0; tm < 2; tm++)
#pragma unroll
        for (int tn = 0; tn < 8; tn++)
#pragma unroll
            for (int q = 0; q < 4; q++) acc[tm][tn][q] = 0.f;

    gemm_pipeline(sm, g_o + (size_t)b * CH * NTOK + m0,
                  g_pw + j0, CH, acc, tid, lane, warp_m, warp_n);

    float* ob = out + (size_t)b * CH * NTOK;
#pragma unroll
    for (int tn = 0; tn < 8; tn++) {
        const int j = j0 + warp_n * 64 + tn * 8 + 2 * (lane & 3);
        const float bv0 = bias[j], bv1 = bias[j + 1];
        float* p0 = ob + (size_t)j * NTOK;
        float* p1 = p0 + NTOK;
#pragma unroll
        for (int tm = 0; tm < 2; tm++) {
            const int n = m0 + warp_m * 32 + tm * 16 + (lane >> 2);
            p0[n]     = acc[tm][tn][0] + bv0;
            p1[n]     = acc[tm][tn][1] + bv1;
            p0[n + 8] = acc[tm][tn][2] + bv0;
            p1[n + 8] = acc[tm][tn][3] + bv1;
        }
    }
}

// ---------------------------------------------------------------------------
extern "C" void kernel_launch(void* const* d_in, const int* in_sizes, int n_in,
                              void* d_out, int out_size)
{
    const float* x      = (const float*)d_in[0];
    const float* w_qkv  = (const float*)d_in[1];
    const float* b_qkv  = (const float*)d_in[2];
    const float* w_proj = (const float*)d_in[3];
    const float* b_proj = (const float*)d_in[4];
    float* out = (float*)d_out;

    cudaFuncSetAttribute(qkv_hmma_kernel,
                         cudaFuncAttributeMaxDynamicSharedMemorySize, GEMM_SMEM);
    cudaFuncSetAttribute(attn_hmma_kernel,
                         cudaFuncAttributeMaxDynamicSharedMemorySize, ATTN_SMEM);
    cudaFuncSetAttribute(proj_hmma_kernel,
                         cudaFuncAttributeMaxDynamicSharedMemorySize, GEMM_SMEM);

    prep_x_kernel<<<(BATCH * CH * NTOK / 4) / 256, 256>>>((const float4*)x);
    prep_w_kernel<<<(CH * TC / 4) / 256, 256>>>((const float4*)w_qkv);
    prep_pw_kernel<<<(CH * CH / 4) / 256, 256>>>((const float4*)w_proj);
    qkv_hmma_kernel<<<dim3(TC / 128, NTOK / 128, BATCH), 256, GEMM_SMEM>>>(b_qkv);
    attn_hmma_kernel<<<dim3(BATCH * NH, NTOK / 128), 256, ATTN_SMEM>>>();
    proj_hmma_kernel<<<dim3(CH / 128, NTOK / 128, BATCH), 256, GEMM_SMEM>>>(b_proj, out);
}

// round 15
// speedup vs baseline: 1.2310x; 1.0459x over previous
#include <cuda_runtime.h>
#include <cuda_fp16.h>
#include <cstdint>

#define BATCH 8
#define CH    512
#define NTOK  1024
#define NH    8
#define HD    64
#define TC    1536
#define ATT_SCALE 0.125f

// fp16 inputs (original layouts)
__device__ __align__(16) __half g_x[BATCH * CH * NTOK];   // [b][k][m]
__device__ __align__(16) __half g_w[CH * TC];             // [k][j]
__device__ __align__(16) __half g_pw[CH * CH];            // [c][j]

// attention operands, written by QKV epilogue
__device__ __align__(16) __half g_q[BATCH * NH * HD * NTOK]; // [b][h][d][n], pre-scaled
__device__ __align__(16) __half g_k[BATCH * NH * HD * NTOK]; // [b][h][d][n]
__device__ __align__(16) __half g_v[BATCH * NH * NTOK * HD]; // [b][h][n][d]
// attention output, transposed: [b][c][n]
__device__ __align__(16) __half g_o[BATCH * CH * NTOK];

__device__ __forceinline__ uint32_t smem_u32(const void* p) {
    uint32_t a;
    asm("{ .reg .u64 t; cvta.to.shared.u64 t, %1; cvt.u32.u64 %0, t; }"
        : "=r"(a) : "l"(p));
    return a;
}
__device__ __forceinline__ void cp16(uint32_t dst, const void* src) {
    asm volatile("cp.async.cg.shared.global [%0], [%1], 16;"
                 :: "r"(dst), "l"(src));
}
#define CP_COMMIT() asm volatile("cp.async.commit_group;" ::: "memory")
#define CP_WAIT1()  asm volatile("cp.async.wait_group 1;" ::: "memory")
#define CP_WAIT0()  asm volatile("cp.async.wait_group 0;" ::: "memory")

__device__ __forceinline__ void ldsm4t(uint32_t* r, uint32_t a) {
    asm volatile("ldmatrix.sync.aligned.m8n8.x4.trans.shared.b16 {%0,%1,%2,%3}, [%4];"
                 : "=r"(r[0]), "=r"(r[1]), "=r"(r[2]), "=r"(r[3]) : "r"(a));
}
__device__ __forceinline__ void mma16816(float* c, const uint32_t* a, const uint32_t* b) {
    asm volatile(
        "mma.sync.aligned.m16n8k16.row.col.f32.f16.f16.f32 "
        "{%0,%1,%2,%3}, {%4,%5,%6,%7}, {%8,%9}, {%0,%1,%2,%3};"
        : "+f"(c[0]), "+f"(c[1]), "+f"(c[2]), "+f"(c[3])
        : "r"(a[0]), "r"(a[1]), "r"(a[2]), "r"(a[3]), "r"(b[0]), "r"(b[1]));
}
__device__ __forceinline__ uint32_t pack_hh(float a, float b) {
    __half2 t = __floats2half2_rn(a, b);
    return *reinterpret_cast<uint32_t*>(&t);
}

// ===================== prep: fp32 -> fp16, single merged kernel =============
#define NX4  (BATCH * CH * NTOK / 4)
#define NW4  (CH * TC / 4)
#define NPW4 (CH * CH / 4)

__global__ void prep_all_kernel(const float4* __restrict__ x,
                                const float4* __restrict__ w,
                                const float4* __restrict__ pw)
{
    int i = blockIdx.x * blockDim.x + threadIdx.x;
    const float4* src;
    uint32_t* dst;
    int j;
    if (i < NX4)                { src = x;  dst = (uint32_t*)g_x;  j = i; }
    else if (i < NX4 + NW4)     { src = w;  dst = (uint32_t*)g_w;  j = i - NX4; }
    else                        { src = pw; dst = (uint32_t*)g_pw; j = i - NX4 - NW4; }
    const float4 v = src[j];
    dst[j * 2]     = pack_hh(v.x, v.y);
    dst[j * 2 + 1] = pack_hh(v.z, v.w);
}

// ============ GEMM body (qkv & proj): 128x128 CTA tile, cp.async ===========
// Stage (32 KB): A[64][256B] +0, B[64][256B] +16384.  K-chunks of 64, 2 stages.
// Warp grid 4(m) x 2(n); warp tile 32 m x 64 j.
__device__ __forceinline__ void gemm_copy_stage(
    uint32_t St, const __half* x, const __half* w,
    int k0, int wstride, int tid)
{
#pragma unroll
    for (int i = 0; i < 4; i++) {
        int q = tid + i * 256, k = q >> 4, c = q & 15;
        uint32_t off = k * 256 + ((c ^ (k & 7)) << 4);
        cp16(St + off, x + (size_t)(k0 + k) * NTOK + c * 8);
    }
#pragma unroll
    for (int i = 0; i < 4; i++) {
        int q = tid + i * 256, k = q >> 4, c = q & 15;
        uint32_t off = k * 256 + ((c ^ (k & 7)) << 4);
        cp16(St + 16384 + off, w + (size_t)(k0 + k) * wstride + c * 8);
    }
}

__device__ __forceinline__ void gemm_pipeline(
    char* sm, const __half* x, const __half* w,
    int wstride, float acc[2][8][4],
    int tid, int lane, int warp_m, int warp_n)
{
    const uint32_t sb = smem_u32(sm);
    const int g = lane >> 3, r8 = lane & 7;

    gemm_copy_stage(sb, x, w, 0, wstride, tid);
    CP_COMMIT();

    for (int ch = 0; ch < 8; ch++) {
        const uint32_t St = sb + (ch & 1) * 32768;
        if (ch < 7) {
            gemm_copy_stage(sb + ((ch + 1) & 1) * 32768, x, w,
                            (ch + 1) * 64, wstride, tid);
            CP_COMMIT();
            CP_WAIT1();
        } else {
            CP_WAIT0();
        }
        __syncthreads();

#pragma unroll
        for (int ks = 0; ks < 4; ks++) {
            uint32_t a[2][4], bb[4][4];
            const int klA = ks * 16 + ((g >> 1) << 3) + r8;
#pragma unroll
            for (int tm = 0; tm < 2; tm++) {
                int cc = ((warp_m * 32 + tm * 16) >> 3) + (g & 1);
                uint32_t off = klA * 256 + ((cc ^ (klA & 7)) << 4);
                ldsm4t(a[tm], St + off);
            }
            const int klB = ks * 16 + ((g & 1) << 3) + r8;
#pragma unroll
            for (int p = 0; p < 4; p++) {
                int cc = ((warp_n * 64 + p * 16) >> 3) + (g >> 1);
                uint32_t off = klB * 256 + ((cc ^ (klB & 7)) << 4);
                ldsm4t(bb[p], St + 16384 + off);
            }
#pragma unroll
            for (int tm = 0; tm < 2; tm++)
#pragma unroll
                for (int tn = 0; tn < 8; tn++)
                    mma16816(acc[tm][tn], a[tm], &bb[tn >> 1][(tn & 1) * 2]);
        }
        __syncthreads();
    }
}

// ===================== Kernel 1: QKV GEMM ==================================
#define GEMM_SMEM 65536

__global__ void __launch_bounds__(256, 2) qkv_hmma_kernel(
    const float* __restrict__ bias)
{
    extern __shared__ char sm[];
    const int tid = threadIdx.x, lane = tid & 31, wid = tid >> 5;
    const int warp_m = wid & 3, warp_n = wid >> 2;
    const int j0 = blockIdx.x * 128, m0 = blockIdx.y * 128, b = blockIdx.z;

    float acc[2][8][4];
#pragma unroll
    for (int tm = 0; tm < 2; tm++)
#pragma unroll
        for (int tn = 0; tn < 8; tn++)
#pragma unroll
            for (int q = 0; q < 4; q++) acc[tm][tn][q] = 0.f;

    gemm_pipeline(sm, g_x + (size_t)b * CH * NTOK + m0,
                  g_w + j0, TC, acc, tid, lane, warp_m, warp_n);

    const int s = j0 >> 9;
#pragma unroll
    for (int tn = 0; tn < 8; tn++) {
        const int j = j0 + warp_n * 64 + tn * 8 + 2 * (lane & 3);
        const int h = (j >> 6) & (NH - 1);
        const int d = j & (HD - 1);
        const int bhh = b * NH + h;
        const float bv0 = bias[j], bv1 = bias[j + 1];
#pragma unroll
        for (int tm = 0; tm < 2; tm++) {
            const int n = m0 + warp_m * 32 + tm * 16 + (lane >> 2);
            float v0 = acc[tm][tn][0] + bv0, v1 = acc[tm][tn][1] + bv1;
            float v2 = acc[tm][tn][2] + bv0, v3 = acc[tm][tn][3] + bv1;
            if (s == 2) {
                size_t a0 = ((size_t)bhh * NTOK + n) * HD + d;
                *(uint32_t*)&g_v[a0] = pack_hh(v0, v1);
                *(uint32_t*)&g_v[a0 + 8 * HD] = pack_hh(v2, v3);
            } else {
                if (s == 0) { v0 *= ATT_SCALE; v1 *= ATT_SCALE; v2 *= ATT_SCALE; v3 *= ATT_SCALE; }
                __half* dq = (s == 0) ? g_q : g_k;
                const size_t b0 = ((size_t)bhh * HD + d) * NTOK;
                const size_t b1 = b0 + NTOK;
                dq[b0 + n]     = __float2half(v0);
                dq[b1 + n]     = __float2half(v1);
                dq[b0 + n + 8] = __float2half(v2);
                dq[b1 + n + 8] = __float2half(v3);
            }
        }
    }
}

// ===================== Kernel 2: Flash attention, KV block 64 ===============
// smem: Q [64][256B] at 0 (16 KB); stage s at 16384 + s*16384:
//   K [64][128B] +0, V [64][128B] +8192.  Total 48 KB -> 2 CTAs/SM.
#define ATTN_SMEM 49152

__device__ __forceinline__ void attn_copy_stage(
    uint32_t St, const __half* k_, const __half* v_, int n0, int tid)
{
#pragma unroll
    for (int i = 0; i < 2; i++) {
        int q = tid + i * 256, k = q >> 3, c = q & 7;      // K: 64 rows(d) x 8
        uint32_t off = k * 128 + ((c ^ (k & 7)) << 4);
        cp16(St + off, k_ + (size_t)k * NTOK + n0 + c * 8);
    }
#pragma unroll
    for (int i = 0; i < 2; i++) {
        int q = tid + i * 256, k = q >> 3, c = q & 7;      // V: 64 rows(n) x 8
        uint32_t off = k * 128 + ((c ^ (k & 7)) << 4);
        cp16(St + 8192 + off, v_ + (size_t)(n0 + k) * HD + c * 8);
    }
}

__global__ void __launch_bounds__(256, 2) attn_hmma_kernel()
{
    extern __shared__ char sm[];
    const uint32_t Qb = smem_u32(sm);

    const int tid = threadIdx.x, lane = tid & 31, w = tid >> 5;
    const int g = lane >> 3, r8 = lane & 7;
    const int bh = blockIdx.x;
    const int m0 = blockIdx.y * 128;

    const __half* qp = g_q + (size_t)bh * HD * NTOK;
    const __half* kp = g_k + (size_t)bh * HD * NTOK;
    const __half* vp = g_v + (size_t)bh * NTOK * HD;

    // prefetch KV block 0 while loading Q
    attn_copy_stage(Qb + 16384, kp, vp, 0, tid);
    CP_COMMIT();

#pragma unroll
    for (int i = 0; i < 4; i++) {
        int q = tid + i * 256, k = q >> 4, c = q & 15;
        uint32_t off = k * 256 + ((c ^ (k & 7)) << 4);
        *(int4*)(sm + off) = *(const int4*)(qp + (size_t)k * NTOK + m0 + c * 8);
    }
    __syncthreads();

    uint32_t aq[4][4];
    {
        const int ccA = 2 * w + (g & 1);
#pragma unroll
        for (int ks = 0; ks < 4; ks++) {
            const int klA = ks * 16 + ((g >> 1) << 3) + r8;
            ldsm4t(aq[ks], Qb + klA * 256 + ((ccA ^ (klA & 7)) << 4));
        }
    }

    float mr0 = -1e30f, mr1 = -1e30f, l0 = 0.f, l1 = 0.f;
    float of[8][4];
#pragma unroll
    for (int tn = 0; tn < 8; tn++)
#pragma unroll
        for (int q = 0; q < 4; q++) of[tn][q] = 0.f;

    for (int nb = 0; nb < 16; nb++) {
        const uint32_t St = Qb + 16384 + (nb & 1) * 16384;
        if (nb < 15) {
            attn_copy_stage(Qb + 16384 + ((nb + 1) & 1) * 16384,
                            kp, vp, (nb + 1) * 64, tid);
            CP_COMMIT();
            CP_WAIT1();
        } else {
            CP_WAIT0();
        }
        __syncthreads();

        const uint32_t Kb = St, Vb = St + 8192;

        // ---- S = Q K^T : 16 rows x 64 keys per warp ----
        float sf[8][4];
#pragma unroll
        for (int t = 0; t < 8; t++)
#pragma unroll
            for (int q = 0; q < 4; q++) sf[t][q] = 0.f;

#pragma unroll
        for (int ks = 0; ks < 4; ks++) {
            const int klB = ks * 16 + ((g & 1) << 3) + r8;
#pragma unroll
            for (int tp = 0; tp < 4; tp++) {
                uint32_t bk[4];
                const int cc = tp * 2 + (g >> 1);
                ldsm4t(bk, Kb + klB * 128 + ((cc ^ (klB & 7)) << 4));
                mma16816(sf[2 * tp],     aq[ks], &bk[0]);
                mma16816(sf[2 * tp + 1], aq[ks], &bk[2]);
            }
        }

        // ---- online softmax over 64 keys ----
        float mx0 = -1e30f, mx1 = -1e30f;
#pragma unroll
        for (int t = 0; t < 8; t++) {
            mx0 = fmaxf(mx0, fmaxf(sf[t][0], sf[t][1]));
            mx1 = fmaxf(mx1, fmaxf(sf[t][2], sf[t][3]));
        }
        mx0 = fmaxf(mx0, __shfl_xor_sync(0xffffffffu, mx0, 1));
        mx0 = fmaxf(mx0, __shfl_xor_sync(0xffffffffu, mx0, 2));
        mx1 = fmaxf(mx1, __shfl_xor_sync(0xffffffffu, mx1, 1));
        mx1 = fmaxf(mx1, __shfl_xor_sync(0xffffffffu, mx1, 2));
        const float nm0 = fmaxf(mr0, mx0), nm1 = fmaxf(mr1, mx1);
        const float a0 = __expf(mr0 - nm0), a1 = __expf(mr1 - nm1);
        mr0 = nm0; mr1 = nm1;
        float rs0 = 0.f, rs1 = 0.f;
#pragma unroll
        for (int t = 0; t < 8; t++) {
            sf[t][0] = __expf(sf[t][0] - nm0);
            sf[t][1] = __expf(sf[t][1] - nm0);
            sf[t][2] = __expf(sf[t][2] - nm1);
            sf[t][3] = __expf(sf[t][3] - nm1);
            rs0 += sf[t][0] + sf[t][1];
            rs1 += sf[t][2] + sf[t][3];
        }
        rs0 += __shfl_xor_sync(0xffffffffu, rs0, 1);
        rs0 += __shfl_xor_sync(0xffffffffu, rs0, 2);
        rs1 += __shfl_xor_sync(0xffffffffu, rs1, 1);
        rs1 += __shfl_xor_sync(0xffffffffu, rs1, 2);
        l0 = l0 * a0 + rs0;
        l1 = l1 * a1 + rs1;
#pragma unroll
        for (int tn = 0; tn < 8; tn++) {
            of[tn][0] *= a0; of[tn][1] *= a0;
            of[tn][2] *= a1; of[tn][3] *= a1;
        }

        // ---- O += P V : 64-key block = 4 k-steps ----
#pragma unroll
        for (int ks = 0; ks < 4; ks++) {
            uint32_t pa[4];
            pa[0] = pack_hh(sf[2 * ks][0],     sf[2 * ks][1]);
            pa[1] = pack_hh(sf[2 * ks][2],     sf[2 * ks][3]);
            pa[2] = pack_hh(sf[2 * ks + 1][0], sf[2 * ks + 1][1]);
            pa[3] = pack_hh(sf[2 * ks + 1][2], sf[2 * ks + 1][3]);
            const int klV = ks * 16 + ((g & 1) << 3) + r8;
#pragma unroll
            for (int tp = 0; tp < 4; tp++) {
                uint32_t bv[4];
                const int cc = tp * 2 + (g >> 1);
                ldsm4t(bv, Vb + klV * 128 + ((cc ^ (klV & 7)) << 4));
                mma16816(of[2 * tp],     pa, &bv[0]);
                mma16816(of[2 * tp + 1], pa, &bv[2]);
            }
        }
        __syncthreads();
    }

    // ---- normalize + write O^T fp16 to g_o [b][c][n] ----
    const int b = bh >> 3, h = bh & 7;
    const float inv0 = 1.f / l0, inv1 = 1.f / l1;
    const int r = w * 16 + (lane >> 2);
    const size_t cbase = ((size_t)b * CH + h * HD) * NTOK;
    const int n = m0 + r;
#pragma unroll
    for (int tn = 0; tn < 8; tn++) {
        const int d = tn * 8 + 2 * (lane & 3);
        const size_t c0 = cbase + (size_t)d * NTOK;
        const size_t c1 = c0 + NTOK;
        g_o[c0 + n]     = __float2half(of[tn][0] * inv0);
        g_o[c1 + n]     = __float2half(of[tn][1] * inv0);
        g_o[c0 + n + 8] = __float2half(of[tn][2] * inv1);
        g_o[c1 + n + 8] = __float2half(of[tn][3] * inv1);
    }
}

// ===================== Kernel 3: Proj GEMM =================================
__global__ void __launch_bounds__(256, 2) proj_hmma_kernel(
    const float* __restrict__ bias, float* __restrict__ out)
{
    extern __shared__ char sm[];
    const int tid = threadIdx.x, lane = tid & 31, wid = tid >> 5;
    const int warp_m = wid & 3, warp_n = wid >> 2;
    const int j0 = blockIdx.x * 128, m0 = blockIdx.y * 128, b = blockIdx.z;

    float acc[2][8][4];
#pragma unroll
    for (int tm = 0; tm < 2; tm++)
#pragma unroll
        for (int tn = 0; tn < 8; tn++)
#pragma unroll
            for (int q = 0; q < 4; q++) acc[tm][tn][q] = 0.f;

    gemm_pipeline(sm, g_o + (size_t)b * CH * NTOK + m0,
                  g_pw + j0, CH, acc, tid, lane, warp_m, warp_n);

    float* ob = out + (size_t)b * CH * NTOK;
#pragma unroll
    for (int tn = 0; tn < 8; tn++) {
        const int j = j0 + warp_n * 64 + tn * 8 + 2 * (lane & 3);
        const float bv0 = bias[j], bv1 = bias[j + 1];
        float* p0 = ob + (size_t)j * NTOK;
        float* p1 = p0 + NTOK;
#pragma unroll
        for (int tm = 0; tm < 2; tm++) {
            const int n = m0 + warp_m * 32 + tm * 16 + (lane >> 2);
            p0[n]     = acc[tm][tn][0] + bv0;
            p1[n]     = acc[tm][tn][1] + bv1;
            p0[n + 8] = acc[tm][tn][2] + bv0;
            p1[n + 8] = acc[tm][tn][3] + bv1;
        }
    }
}

// ---------------------------------------------------------------------------
extern "C" void kernel_launch(void* const* d_in, const int* in_sizes, int n_in,
                              void* d_out, int out_size)
{
    const float* x      = (const float*)d_in[0];
    const float* w_qkv  = (const float*)d_in[1];
    const float* b_qkv  = (const float*)d_in[2];
    const float* w_proj = (const float*)d_in[3];
    const float* b_proj = (const float*)d_in[4];
    float* out = (float*)d_out;

    cudaFuncSetAttribute(qkv_hmma_kernel,
                         cudaFuncAttributeMaxDynamicSharedMemorySize, GEMM_SMEM);
    cudaFuncSetAttribute(attn_hmma_kernel,
                         cudaFuncAttributeMaxDynamicSharedMemorySize, ATTN_SMEM);
    cudaFuncSetAttribute(proj_hmma_kernel,
                         cudaFuncAttributeMaxDynamicSharedMemorySize, GEMM_SMEM);

    prep_all_kernel<<<(NX4 + NW4 + NPW4) / 256, 256>>>(
        (const float4*)x, (const float4*)w_qkv, (const float4*)w_proj);
    qkv_hmma_kernel<<<dim3(TC / 128, NTOK / 128, BATCH), 256, GEMM_SMEM>>>(b_qkv);
    attn_hmma_kernel<<<dim3(BATCH * NH, NTOK / 128), 256, ATTN_SMEM>>>();
    proj_hmma_kernel<<<dim3(CH / 128, NTOK / 128, BATCH), 256, GEMM_SMEM>>>(b_proj, out);
}